// round 13
// baseline (speedup 1.0000x reference)
#include <cuda_runtime.h>

// ---------------------------------------------------------------------------
// LocalGOCorrOpt: fused steepest-descent filter optimization.
// b=4, c=128, H=W=128, 9x9 search window (81 disps), 10 bins, 3 iterations.
// R12: packed fma.rn.f32x2 inner loops (2 FMA/instr); corr_t widened to
// 256 threads; no forced reg caps (R11 cap caused spills).
// ---------------------------------------------------------------------------

#define NB 4
#define NC 128
#define NH 128
#define NW 128
#define NHW (NH*NW)
#define NS 9
#define ND 81
#define TX 32
#define TY 8
#define RST 44         // padded smem stride for ref window rows
#define FST 36         // padded smem stride for f / mapped rows

// ---------------- device scratch (no allocation allowed) -------------------
__device__ float g_scores[NB*ND*NHW];     // (b,81,H,W)
__device__ float g_fgrad[NB*NC*NHW];      // (b,c,H,W)
__device__ float g_f[NB*NC*NHW];          // current filter between iterations
__device__ float g_anum[NB*NHW];          // alpha numerator per pixel
__device__ float g_target[ND];
__device__ float g_vplus[ND];
__device__ float g_alo[ND];
__device__ float g_ahi[ND];
__device__ float g_step;
__device__ float g_reg;

typedef unsigned long long u64;

// ---------------- packed f32x2 helpers -------------------------------------
__device__ __forceinline__ u64 pk2(float lo, float hi) {
    u64 r; asm("mov.b64 %0, {%1, %2};" : "=l"(r) : "f"(lo), "f"(hi)); return r;
}
__device__ __forceinline__ u64 fma2(u64 a, u64 b, u64 c) {
    u64 d; asm("fma.rn.f32x2 %0, %1, %2, %3;" : "=l"(d) : "l"(a), "l"(b), "l"(c));
    return d;
}
__device__ __forceinline__ float2 upk2(u64 v) {
    float2 f; asm("mov.b64 {%0, %1}, %2;" : "=f"(f.x), "=f"(f.y) : "l"(v));
    return f;
}

// ---------------- per-displacement constants -------------------------------
__global__ void setup_kernel(const float* __restrict__ lw, const float* __restrict__ sw,
                             const float* __restrict__ mw, const float* __restrict__ ls,
                             const float* __restrict__ fr) {
    int d = threadIdx.x;
    if (d == 0) {
        g_step = expf(ls[0]);
        float rr = fr[0] * fr[0];
        g_reg = fmaxf(rr, 1e-10f) / (float)(NC * NC);
    }
    if (d < ND) {
        int dy = d / NS, dx = d % NS;
        float fy = (float)dy - 4.0f, fx = (float)dx - 4.0f;
        float dist = sqrtf(fy*fy + fx*fx) * 2.0f;   // / bin_displacement (0.5)
        float t = 0.f, vp = 0.f, m = 0.f;
        for (int k = 0; k < 10; k++) {
            float val;
            if (k == 9) val = fminf(fmaxf(dist - 8.0f, 0.0f), 1.0f);
            else        val = fmaxf(1.0f - fabsf(dist - (float)k), 0.0f);
            t  += val * lw[k];
            vp += val * sw[k];
            m  += val * mw[k];
        }
        float wm = 1.0f / (1.0f + expf(-m));        // sigmoid
        g_target[d] = t;
        g_vplus[d]  = vp;
        g_alo[d]    = (1.0f - wm) * 0.5f;
        g_ahi[d]    = (1.0f + wm) * 0.5f;
    }
}

// ---------------- cp.async helpers -----------------------------------------
__device__ __forceinline__ void cpa16(float* dst, const float* src, bool v) {
    unsigned s = (unsigned)__cvta_generic_to_shared(dst);
    int n = v ? 16 : 0;                  // src-size 0 -> zero-fill destination
    asm volatile("cp.async.cg.shared.global [%0], [%1], 16, %2;\n"
                 :: "r"(s), "l"(src), "r"(n));
}
__device__ __forceinline__ void cp_commit() {
    asm volatile("cp.async.commit_group;\n");
}
template<int N> __device__ __forceinline__ void cp_wait() {
    asm volatile("cp.async.wait_group %0;\n" :: "n"(N));
}
// i / 160 for 0 <= i < 4096
__device__ __forceinline__ int div160(int i) {
    return (int)(((unsigned)i * 52429u) >> 23);
}

// Build per-block ref-window staging table: for each of the 160 float4 slots
// of one channel's window: x = global spatial offset (or -1 if OOB zero-fill),
// y = smem offset within the channel's 704-float region.
__device__ __forceinline__ void build_ref_tbl(int2* tbl, int tid, int nthr,
                                              int x0, int y0) {
    for (int i = tid; i < 160; i += nthr) {
        int wy = i / 10, wx4 = i - wy*10;
        int h = y0 + wy - 4, w = x0 + wx4*4 - 4;
        bool v = ((unsigned)h < NH) && ((unsigned)w < NW);
        tbl[i] = make_int2(v ? (h*NW + w) : -1, wy*RST + wx4*4);
    }
}

// ---------------------------------------------------------------------------
// corr_kernel: scores(p,d) = sum_c f(c,p) * ref(c, p+d-4)
// 288 threads = 9 warps; warp w handles dy=w; thread tile = 8 px (x) * 9 dx,
// accumulated as 4 f32x2 pairs per dx. Channels streamed in 8-ch chunks,
// cp.async double-buffered.
// MODE 0: write g_scores.
// MODE 1: fin = f_grad; epilogue reduces alpha_den in smem, computes alpha,
//         and applies the filter update (fout = fbase - step*alpha*f_grad).
// ---------------------------------------------------------------------------
#define CORR_SMEM (15872*4 + 160*8)

template<int MODE>
__global__ __launch_bounds__(288)
void corr_kernel(const float* __restrict__ fin, const float* __restrict__ ref,
                 const float* __restrict__ fbase, float* __restrict__ fout)
{
    extern __shared__ float sm[];
    int2* tbl = (int2*)(sm + 15872);
    const int b  = blockIdx.z;
    const int x0 = blockIdx.x * TX, y0 = blockIdx.y * TY;
    const int tid = threadIdx.x;
    const int dy = tid >> 5;
    const int r  = tid & 31;
    const int y  = r >> 2;
    const int xg = r & 3;

    build_ref_tbl(tbl, tid, 288, x0, y0);

    const float* refb = ref + b*NC*NHW;
    const float* finb = fin + ((b*NC)*NH + y0)*NW + x0;

    u64 acc2[9][4];
#pragma unroll
    for (int a = 0; a < 9; a++)
#pragma unroll
        for (int p = 0; p < 4; p++) acc2[a][p] = 0ull;

#define STAGE_CORR(s, ch) do {                                                 \
        float* rb_ = sm + (s)*7936;                                            \
        float* fb_ = rb_ + 5632;                                               \
        const float* rc_ = refb + (ch)*NHW;                                    \
        _Pragma("unroll")                                                      \
        for (int k_ = 0; k_ < 5; k_++) {                                       \
            int i_ = tid + k_*288;                                             \
            if (i_ < 1280) {                                                   \
                int c_ = div160(i_);                                           \
                int2 t_ = tbl[i_ - c_*160];                                    \
                bool v_ = (t_.x >= 0);                                         \
                const float* src_ = v_ ? (rc_ + c_*NHW + t_.x) : rc_;          \
                cpa16(rb_ + c_*704 + t_.y, src_, v_);                          \
            }                                                                  \
        }                                                                      \
        _Pragma("unroll")                                                      \
        for (int k_ = 0; k_ < 2; k_++) {                                       \
            int i_ = tid + k_*288;                                             \
            if (i_ < 512) {                                                    \
                int c_ = i_ >> 6, rem_ = i_ & 63;                              \
                int yy_ = rem_ >> 3, x4_ = rem_ & 7;                           \
                cpa16(fb_ + c_*288 + yy_*36 + x4_*4,                           \
                      finb + ((ch) + c_)*NHW + yy_*NW + x4_*4, true);          \
            }                                                                  \
        }                                                                      \
        cp_commit();                                                           \
    } while (0)

    __syncthreads();      // table ready
    STAGE_CORR(0, 0);

    for (int ci = 0; ci < 16; ci++) {
        if (ci < 15) { STAGE_CORR((ci+1)&1, (ci+1)*8); cp_wait<1>(); }
        else         { cp_wait<0>(); }
        __syncthreads();
        const float* rbuf = sm + (ci & 1)*7936;
        const float* fbuf = rbuf + 5632;
#pragma unroll
        for (int cl = 0; cl < 8; cl++) {
            const float4* rp = (const float4*)(rbuf + cl*704 + (y+dy)*RST + xg*8);
            float4 ra = rp[0], rb4 = rp[1], rc4 = rp[2], rd4 = rp[3];
            float rv[16] = {ra.x,ra.y,ra.z,ra.w, rb4.x,rb4.y,rb4.z,rb4.w,
                            rc4.x,rc4.y,rc4.z,rc4.w, rd4.x,rd4.y,rd4.z,rd4.w};
            u64 rvp[15];
#pragma unroll
            for (int k = 0; k < 15; k++) rvp[k] = pk2(rv[k], rv[k+1]);
            const ulonglong2* fq = (const ulonglong2*)(fbuf + cl*288 + y*36 + xg*8);
            ulonglong2 fA = fq[0], fB = fq[1];
            u64 fvp[4] = {fA.x, fA.y, fB.x, fB.y};
#pragma unroll
            for (int dx = 0; dx < 9; dx++)
#pragma unroll
                for (int p = 0; p < 4; p++)
                    acc2[dx][p] = fma2(fvp[p], rvp[dx + 2*p], acc2[dx][p]);
        }
        __syncthreads();
    }
#undef STAGE_CORR

    const int gh = y0 + y, gw = x0 + xg*8;
    if (MODE == 0) {
#pragma unroll
        for (int dx = 0; dx < 9; dx++) {
            int d = dy*9 + dx;
            float2 u0 = upk2(acc2[dx][0]), u1 = upk2(acc2[dx][1]);
            float2 u2 = upk2(acc2[dx][2]), u3 = upk2(acc2[dx][3]);
            float4* outp = (float4*)(g_scores + ((b*ND + d)*NH + gh)*NW + gw);
            outp[0] = make_float4(u0.x, u0.y, u1.x, u1.y);
            outp[1] = make_float4(u2.x, u2.y, u3.x, u3.y);
        }
    } else {
        // ---- alpha_den = sum_d sg^2, reduced across the 9 dy-warps --------
        float den[8];
#pragma unroll
        for (int j = 0; j < 8; j++) den[j] = 0.f;
#pragma unroll
        for (int dx = 0; dx < 9; dx++) {
            int d = dy*9 + dx;
            float vp = g_vplus[d], alo = g_alo[d], ahi = g_ahi[d];
            float2 u0 = upk2(acc2[dx][0]), u1 = upk2(acc2[dx][1]);
            float2 u2 = upk2(acc2[dx][2]), u3 = upk2(acc2[dx][3]);
            float av[8] = {u0.x,u0.y,u1.x,u1.y, u2.x,u2.y,u3.x,u3.y};
            const float4* sp = (const float4*)(g_scores + ((b*ND + d)*NH + gh)*NW + gw);
            float4 sa = sp[0], sb = sp[1];
            float sv[8] = {sa.x,sa.y,sa.z,sa.w, sb.x,sb.y,sb.z,sb.w};
#pragma unroll
            for (int j = 0; j < 8; j++) {
                float s = sv[j];
                float sgn = (s > 0.f) ? 1.f : ((s < 0.f) ? -1.f : 0.f);
                float ga = vp * (alo*sgn + ahi);         // grad_act
                float sg = ga * av[j];
                den[j] = fmaf(sg, sg, den[j]);
            }
        }
        float* denS   = sm;        // reuse staging smem
        float* alphaS = sm + 256;
        __syncthreads();
        if (tid < 256) denS[tid] = 0.f;
        __syncthreads();
#pragma unroll
        for (int j = 0; j < 8; j++)
            atomicAdd(denS + (y*32 + xg*8 + j), den[j]);
        __syncthreads();
        if (tid < 256) {
            int py = tid >> 5, px = tid & 31;
            float num = g_anum[b*NHW + (y0 + py)*NW + x0 + px];
            float dn  = denS[tid];
            alphaS[tid] = g_step * (num / fmaxf(dn + g_reg*num, 1e-8f));
        }
        __syncthreads();
        // ---- fused filter update: fout = fbase - (step*alpha) * f_grad ----
        for (int i = tid; i < 8192; i += 288) {
            int c = i >> 6, rem = i & 63, py = rem >> 3, x4 = rem & 7;
            int gi = ((b*NC + c)*NH + y0 + py)*NW + x0 + x4*4;
            float4 fv4 = *(const float4*)(fbase + gi);
            float4 gv4 = *(const float4*)(fin + gi);     // fin == f_grad here
            float4 sa  = *(const float4*)(alphaS + py*32 + x4*4);
            float4 o;
            o.x = fv4.x - sa.x*gv4.x;
            o.y = fv4.y - sa.y*gv4.y;
            o.z = fv4.z - sa.z*gv4.z;
            o.w = fv4.w - sa.w*gv4.w;
            *(float4*)(fout + gi) = o;
        }
    }
}

// ---------------------------------------------------------------------------
// corr_t_kernel: f_grad(c,p) = reg*f(c,p) + sum_d mapped(d,p)*ref(c,p+d-4)
// 256 threads = 8 warps; warp cg handles 2 channels of a 16-channel chunk.
// mapped cached once in smem (pairs load free as u64); ref cp.async
// double-buffered (16-ch chunks). Inner loop in f32x2.
// Also writes alpha_num = sum_c f_grad^2 (in-block smem reduction).
// ---------------------------------------------------------------------------
#define CT_SMEM (45856*4 + 160*8)

__global__ __launch_bounds__(256)
void corr_t_kernel(const float* __restrict__ fin, const float* __restrict__ ref)
{
    extern __shared__ float sm[];
    float* mS = sm;                        // 81*8*36 = 23328 floats
    int2* tbl = (int2*)(sm + 45856);
    const int b  = blockIdx.z;
    const int x0 = blockIdx.x * TX, y0 = blockIdx.y * TY;
    const int tid = threadIdx.x;
    const int cg = tid >> 5;               // warp id 0..7
    const int r  = tid & 31;
    const int y  = r >> 2;
    const int xg = r & 3;
    const float regw = g_reg;

    build_ref_tbl(tbl, tid, 256, x0, y0);
    __syncthreads();

    const float* refb = ref + b*NC*NHW;

#define STAGE_CT(s, ch) do {                                                   \
        float* rb_ = sm + 23328 + (s)*11264;                                   \
        const float* rc_ = refb + (ch)*NHW;                                    \
        _Pragma("unroll")                                                      \
        for (int k_ = 0; k_ < 10; k_++) {                                      \
            int i_ = tid + k_*256;                                             \
            int c_ = div160(i_);                                               \
            int2 t_ = tbl[i_ - c_*160];                                        \
            bool v_ = (t_.x >= 0);                                             \
            const float* src_ = v_ ? (rc_ + c_*NHW + t_.x) : rc_;              \
            cpa16(rb_ + c_*704 + t_.y, src_, v_);                              \
        }                                                                      \
        cp_commit();                                                           \
    } while (0)

    STAGE_CT(0, 0);   // prefetch first ref chunk, overlaps with mS staging

    // stage mapped = grad_act * (act - v_plus*target) for all (d, pixel)
    for (int i = tid; i < ND*256; i += 256) {
        int d = i >> 8, p = i & 255, py = p >> 5, px = p & 31;
        float s = g_scores[((b*ND + d)*NH + y0 + py)*NW + x0 + px];
        float vp = g_vplus[d], alo = g_alo[d], ahi = g_ahi[d], tg = g_target[d];
        float sgn = (s > 0.f) ? 1.f : ((s < 0.f) ? -1.f : 0.f);
        float ga  = vp * (alo*sgn + ahi);
        float act = vp * (alo*fabsf(s) + ahi*s);
        mS[d*(TY*FST) + py*FST + px] = ga * (act - vp*tg);
    }

    float anum[8];
#pragma unroll
    for (int j = 0; j < 8; j++) anum[j] = 0.f;
    const int gh = y0 + y, gw = x0 + xg*8;

    for (int ci = 0; ci < 8; ci++) {
        if (ci < 7) { STAGE_CT((ci+1)&1, (ci+1)*16); cp_wait<1>(); }
        else        { cp_wait<0>(); }
        __syncthreads();
        const float* rbuf = sm + 23328 + (ci & 1)*11264;

        u64 acc2[2][4];
#pragma unroll
        for (int a = 0; a < 2; a++)
#pragma unroll
            for (int p = 0; p < 4; p++) acc2[a][p] = 0ull;

        for (int dyy = 0; dyy < 9; dyy++) {
            u64 mvp[9][4];
#pragma unroll
            for (int dx = 0; dx < 9; dx++) {
                const ulonglong2* mp = (const ulonglong2*)
                    (mS + (dyy*9 + dx)*(TY*FST) + y*FST + xg*8);
                ulonglong2 m0 = mp[0], m1 = mp[1];
                mvp[dx][0] = m0.x; mvp[dx][1] = m0.y;
                mvp[dx][2] = m1.x; mvp[dx][3] = m1.y;
            }
#pragma unroll
            for (int cl = 0; cl < 2; cl++) {
                const float4* rp = (const float4*)
                    (rbuf + (cg*2 + cl)*704 + (y + dyy)*RST + xg*8);
                float4 ra = rp[0], rb4 = rp[1], rc4 = rp[2], rd4 = rp[3];
                float rv[16] = {ra.x,ra.y,ra.z,ra.w, rb4.x,rb4.y,rb4.z,rb4.w,
                                rc4.x,rc4.y,rc4.z,rc4.w, rd4.x,rd4.y,rd4.z,rd4.w};
                u64 rvp[15];
#pragma unroll
                for (int k = 0; k < 15; k++) rvp[k] = pk2(rv[k], rv[k+1]);
#pragma unroll
                for (int dx = 0; dx < 9; dx++)
#pragma unroll
                    for (int p = 0; p < 4; p++)
                        acc2[cl][p] = fma2(mvp[dx][p], rvp[dx + 2*p], acc2[cl][p]);
            }
        }

        // finalize this chunk's 2 channels: add reg*f, write f_grad, alpha_num
#pragma unroll
        for (int cl = 0; cl < 2; cl++) {
            int c = ci*16 + cg*2 + cl;
            int gi = ((b*NC + c)*NH + gh)*NW + gw;
            float2 u0 = upk2(acc2[cl][0]), u1 = upk2(acc2[cl][1]);
            float2 u2 = upk2(acc2[cl][2]), u3 = upk2(acc2[cl][3]);
            float av[8] = {u0.x,u0.y,u1.x,u1.y, u2.x,u2.y,u3.x,u3.y};
            const float4* fp = (const float4*)(fin + gi);
            float4 fa = fp[0], fb4 = fp[1];
            float fv[8] = {fa.x,fa.y,fa.z,fa.w, fb4.x,fb4.y,fb4.z,fb4.w};
            float fg[8];
#pragma unroll
            for (int j = 0; j < 8; j++) fg[j] = fmaf(regw, fv[j], av[j]);
            float4* op = (float4*)(g_fgrad + gi);
            op[0] = make_float4(fg[0], fg[1], fg[2], fg[3]);
            op[1] = make_float4(fg[4], fg[5], fg[6], fg[7]);
#pragma unroll
            for (int j = 0; j < 8; j++) anum[j] = fmaf(fg[j], fg[j], anum[j]);
        }
        __syncthreads();
    }
#undef STAGE_CT

    // reduce alpha_num across the 8 warps (channels), write to global
    float* numS = sm;      // reuse mS region (all compute done)
    numS[tid] = 0.f;
    __syncthreads();
#pragma unroll
    for (int j = 0; j < 8; j++)
        atomicAdd(numS + (y*32 + xg*8 + j), anum[j]);
    __syncthreads();
    if (tid < 256)
        g_anum[b*NHW + (y0 + (tid >> 5))*NW + x0 + (tid & 31)] = numS[tid];
}

// ---------------------------------------------------------------------------
extern "C" void kernel_launch(void* const* d_in, const int* in_sizes, int n_in,
                              void* d_out, int out_size) {
    const float* fmap = (const float*)d_in[0];   // filter_map (b,c,H,W)
    const float* ref  = (const float*)d_in[1];   // reference_feat (b,c,H,W)
    const float* lw   = (const float*)d_in[2];   // label_w (10)
    const float* sw   = (const float*)d_in[3];   // spatial_w (10)
    const float* mw   = (const float*)d_in[4];   // mask_w (10)
    const float* ls   = (const float*)d_in[5];   // log_step_length (1)
    const float* fr   = (const float*)d_in[6];   // filter_reg (1)
    float* out = (float*)d_out;

    cudaFuncSetAttribute(corr_kernel<0>,
                         cudaFuncAttributeMaxDynamicSharedMemorySize, CORR_SMEM);
    cudaFuncSetAttribute(corr_kernel<1>,
                         cudaFuncAttributeMaxDynamicSharedMemorySize, CORR_SMEM);
    cudaFuncSetAttribute(corr_t_kernel,
                         cudaFuncAttributeMaxDynamicSharedMemorySize, CT_SMEM);

    void* p;
    cudaGetSymbolAddress(&p, g_f);     float* gf  = (float*)p;
    cudaGetSymbolAddress(&p, g_fgrad); float* gfg = (float*)p;

    setup_kernel<<<1, 128>>>(lw, sw, mw, ls, fr);

    dim3 grid(NW/TX, NH/TY, NB);   // (4, 16, 4)
    for (int it = 0; it < 3; it++) {
        const float* fin = (it == 0) ? fmap : gf;
        float* fout = (it == 2) ? out : gf;
        corr_kernel<0><<<grid, 288, CORR_SMEM>>>(fin, ref, nullptr, nullptr);  // scores
        corr_t_kernel<<<grid, 256, CT_SMEM>>>(fin, ref);           // f_grad + alpha_num
        corr_kernel<1><<<grid, 288, CORR_SMEM>>>(gfg, ref, fin, fout); // alpha_den + update
    }
}

// round 14
// speedup vs baseline: 1.0033x; 1.0033x over previous
#include <cuda_runtime.h>

// ---------------------------------------------------------------------------
// LocalGOCorrOpt: fused steepest-descent filter optimization.
// b=4, c=128, H=W=128, 9x9 search window (81 disps), 10 bins, 3 iterations.
// R12: packed fma.rn.f32x2 inner loops (2 FMA/instr); corr_t widened to
// 256 threads; no forced reg caps (R11 cap caused spills).
// ---------------------------------------------------------------------------

#define NB 4
#define NC 128
#define NH 128
#define NW 128
#define NHW (NH*NW)
#define NS 9
#define ND 81
#define TX 32
#define TY 8
#define RST 44         // padded smem stride for ref window rows
#define FST 36         // padded smem stride for f / mapped rows

// ---------------- device scratch (no allocation allowed) -------------------
__device__ float g_scores[NB*ND*NHW];     // (b,81,H,W)
__device__ float g_fgrad[NB*NC*NHW];      // (b,c,H,W)
__device__ float g_f[NB*NC*NHW];          // current filter between iterations
__device__ float g_anum[NB*NHW];          // alpha numerator per pixel
__device__ float g_target[ND];
__device__ float g_vplus[ND];
__device__ float g_alo[ND];
__device__ float g_ahi[ND];
__device__ float g_step;
__device__ float g_reg;

typedef unsigned long long u64;

// ---------------- packed f32x2 helpers -------------------------------------
__device__ __forceinline__ u64 pk2(float lo, float hi) {
    u64 r; asm("mov.b64 %0, {%1, %2};" : "=l"(r) : "f"(lo), "f"(hi)); return r;
}
__device__ __forceinline__ u64 fma2(u64 a, u64 b, u64 c) {
    u64 d; asm("fma.rn.f32x2 %0, %1, %2, %3;" : "=l"(d) : "l"(a), "l"(b), "l"(c));
    return d;
}
__device__ __forceinline__ float2 upk2(u64 v) {
    float2 f; asm("mov.b64 {%0, %1}, %2;" : "=f"(f.x), "=f"(f.y) : "l"(v));
    return f;
}

// ---------------- per-displacement constants -------------------------------
__global__ void setup_kernel(const float* __restrict__ lw, const float* __restrict__ sw,
                             const float* __restrict__ mw, const float* __restrict__ ls,
                             const float* __restrict__ fr) {
    int d = threadIdx.x;
    if (d == 0) {
        g_step = expf(ls[0]);
        float rr = fr[0] * fr[0];
        g_reg = fmaxf(rr, 1e-10f) / (float)(NC * NC);
    }
    if (d < ND) {
        int dy = d / NS, dx = d % NS;
        float fy = (float)dy - 4.0f, fx = (float)dx - 4.0f;
        float dist = sqrtf(fy*fy + fx*fx) * 2.0f;   // / bin_displacement (0.5)
        float t = 0.f, vp = 0.f, m = 0.f;
        for (int k = 0; k < 10; k++) {
            float val;
            if (k == 9) val = fminf(fmaxf(dist - 8.0f, 0.0f), 1.0f);
            else        val = fmaxf(1.0f - fabsf(dist - (float)k), 0.0f);
            t  += val * lw[k];
            vp += val * sw[k];
            m  += val * mw[k];
        }
        float wm = 1.0f / (1.0f + expf(-m));        // sigmoid
        g_target[d] = t;
        g_vplus[d]  = vp;
        g_alo[d]    = (1.0f - wm) * 0.5f;
        g_ahi[d]    = (1.0f + wm) * 0.5f;
    }
}

// ---------------- cp.async helpers -----------------------------------------
__device__ __forceinline__ void cpa16(float* dst, const float* src, bool v) {
    unsigned s = (unsigned)__cvta_generic_to_shared(dst);
    int n = v ? 16 : 0;                  // src-size 0 -> zero-fill destination
    asm volatile("cp.async.cg.shared.global [%0], [%1], 16, %2;\n"
                 :: "r"(s), "l"(src), "r"(n));
}
__device__ __forceinline__ void cp_commit() {
    asm volatile("cp.async.commit_group;\n");
}
template<int N> __device__ __forceinline__ void cp_wait() {
    asm volatile("cp.async.wait_group %0;\n" :: "n"(N));
}
// i / 160 for 0 <= i < 4096
__device__ __forceinline__ int div160(int i) {
    return (int)(((unsigned)i * 52429u) >> 23);
}

// Build per-block ref-window staging table: for each of the 160 float4 slots
// of one channel's window: x = global spatial offset (or -1 if OOB zero-fill),
// y = smem offset within the channel's 704-float region.
__device__ __forceinline__ void build_ref_tbl(int2* tbl, int tid, int nthr,
                                              int x0, int y0) {
    for (int i = tid; i < 160; i += nthr) {
        int wy = i / 10, wx4 = i - wy*10;
        int h = y0 + wy - 4, w = x0 + wx4*4 - 4;
        bool v = ((unsigned)h < NH) && ((unsigned)w < NW);
        tbl[i] = make_int2(v ? (h*NW + w) : -1, wy*RST + wx4*4);
    }
}

// ---------------------------------------------------------------------------
// corr_kernel: scores(p,d) = sum_c f(c,p) * ref(c, p+d-4)
// 288 threads = 9 warps; warp w handles dy=w; thread tile = 8 px (x) * 9 dx,
// accumulated as 4 f32x2 pairs per dx. Channels streamed in 8-ch chunks,
// cp.async double-buffered.
// MODE 0: write g_scores.
// MODE 1: fin = f_grad; epilogue reduces alpha_den in smem, computes alpha,
//         and applies the filter update (fout = fbase - step*alpha*f_grad).
// ---------------------------------------------------------------------------
#define CORR_SMEM (15872*4 + 160*8)

template<int MODE>
__global__ __launch_bounds__(288)
void corr_kernel(const float* __restrict__ fin, const float* __restrict__ ref,
                 const float* __restrict__ fbase, float* __restrict__ fout)
{
    extern __shared__ float sm[];
    int2* tbl = (int2*)(sm + 15872);
    const int b  = blockIdx.z;
    const int x0 = blockIdx.x * TX, y0 = blockIdx.y * TY;
    const int tid = threadIdx.x;
    const int dy = tid >> 5;
    const int r  = tid & 31;
    const int y  = r >> 2;
    const int xg = r & 3;

    build_ref_tbl(tbl, tid, 288, x0, y0);

    const float* refb = ref + b*NC*NHW;
    const float* finb = fin + ((b*NC)*NH + y0)*NW + x0;

    u64 acc2[9][4];
#pragma unroll
    for (int a = 0; a < 9; a++)
#pragma unroll
        for (int p = 0; p < 4; p++) acc2[a][p] = 0ull;

#define STAGE_CORR(s, ch) do {                                                 \
        float* rb_ = sm + (s)*7936;                                            \
        float* fb_ = rb_ + 5632;                                               \
        const float* rc_ = refb + (ch)*NHW;                                    \
        _Pragma("unroll")                                                      \
        for (int k_ = 0; k_ < 5; k_++) {                                       \
            int i_ = tid + k_*288;                                             \
            if (i_ < 1280) {                                                   \
                int c_ = div160(i_);                                           \
                int2 t_ = tbl[i_ - c_*160];                                    \
                bool v_ = (t_.x >= 0);                                         \
                const float* src_ = v_ ? (rc_ + c_*NHW + t_.x) : rc_;          \
                cpa16(rb_ + c_*704 + t_.y, src_, v_);                          \
            }                                                                  \
        }                                                                      \
        _Pragma("unroll")                                                      \
        for (int k_ = 0; k_ < 2; k_++) {                                       \
            int i_ = tid + k_*288;                                             \
            if (i_ < 512) {                                                    \
                int c_ = i_ >> 6, rem_ = i_ & 63;                              \
                int yy_ = rem_ >> 3, x4_ = rem_ & 7;                           \
                cpa16(fb_ + c_*288 + yy_*36 + x4_*4,                           \
                      finb + ((ch) + c_)*NHW + yy_*NW + x4_*4, true);          \
            }                                                                  \
        }                                                                      \
        cp_commit();                                                           \
    } while (0)

    __syncthreads();      // table ready
    STAGE_CORR(0, 0);

    for (int ci = 0; ci < 16; ci++) {
        if (ci < 15) { STAGE_CORR((ci+1)&1, (ci+1)*8); cp_wait<1>(); }
        else         { cp_wait<0>(); }
        __syncthreads();
        const float* rbuf = sm + (ci & 1)*7936;
        const float* fbuf = rbuf + 5632;
#pragma unroll
        for (int cl = 0; cl < 8; cl++) {
            const float4* rp = (const float4*)(rbuf + cl*704 + (y+dy)*RST + xg*8);
            float4 ra = rp[0], rb4 = rp[1], rc4 = rp[2], rd4 = rp[3];
            float rv[16] = {ra.x,ra.y,ra.z,ra.w, rb4.x,rb4.y,rb4.z,rb4.w,
                            rc4.x,rc4.y,rc4.z,rc4.w, rd4.x,rd4.y,rd4.z,rd4.w};
            u64 rvp[15];
#pragma unroll
            for (int k = 0; k < 15; k++) rvp[k] = pk2(rv[k], rv[k+1]);
            const ulonglong2* fq = (const ulonglong2*)(fbuf + cl*288 + y*36 + xg*8);
            ulonglong2 fA = fq[0], fB = fq[1];
            u64 fvp[4] = {fA.x, fA.y, fB.x, fB.y};
#pragma unroll
            for (int dx = 0; dx < 9; dx++)
#pragma unroll
                for (int p = 0; p < 4; p++)
                    acc2[dx][p] = fma2(fvp[p], rvp[dx + 2*p], acc2[dx][p]);
        }
        __syncthreads();
    }
#undef STAGE_CORR

    const int gh = y0 + y, gw = x0 + xg*8;
    if (MODE == 0) {
#pragma unroll
        for (int dx = 0; dx < 9; dx++) {
            int d = dy*9 + dx;
            float2 u0 = upk2(acc2[dx][0]), u1 = upk2(acc2[dx][1]);
            float2 u2 = upk2(acc2[dx][2]), u3 = upk2(acc2[dx][3]);
            float4* outp = (float4*)(g_scores + ((b*ND + d)*NH + gh)*NW + gw);
            outp[0] = make_float4(u0.x, u0.y, u1.x, u1.y);
            outp[1] = make_float4(u2.x, u2.y, u3.x, u3.y);
        }
    } else {
        // ---- alpha_den = sum_d sg^2, reduced across the 9 dy-warps --------
        float den[8];
#pragma unroll
        for (int j = 0; j < 8; j++) den[j] = 0.f;
#pragma unroll
        for (int dx = 0; dx < 9; dx++) {
            int d = dy*9 + dx;
            float vp = g_vplus[d], alo = g_alo[d], ahi = g_ahi[d];
            float2 u0 = upk2(acc2[dx][0]), u1 = upk2(acc2[dx][1]);
            float2 u2 = upk2(acc2[dx][2]), u3 = upk2(acc2[dx][3]);
            float av[8] = {u0.x,u0.y,u1.x,u1.y, u2.x,u2.y,u3.x,u3.y};
            const float4* sp = (const float4*)(g_scores + ((b*ND + d)*NH + gh)*NW + gw);
            float4 sa = sp[0], sb = sp[1];
            float sv[8] = {sa.x,sa.y,sa.z,sa.w, sb.x,sb.y,sb.z,sb.w};
#pragma unroll
            for (int j = 0; j < 8; j++) {
                float s = sv[j];
                float sgn = (s > 0.f) ? 1.f : ((s < 0.f) ? -1.f : 0.f);
                float ga = vp * (alo*sgn + ahi);         // grad_act
                float sg = ga * av[j];
                den[j] = fmaf(sg, sg, den[j]);
            }
        }
        float* denS   = sm;        // reuse staging smem
        float* alphaS = sm + 256;
        __syncthreads();
        if (tid < 256) denS[tid] = 0.f;
        __syncthreads();
#pragma unroll
        for (int j = 0; j < 8; j++)
            atomicAdd(denS + (y*32 + xg*8 + j), den[j]);
        __syncthreads();
        if (tid < 256) {
            int py = tid >> 5, px = tid & 31;
            float num = g_anum[b*NHW + (y0 + py)*NW + x0 + px];
            float dn  = denS[tid];
            alphaS[tid] = g_step * (num / fmaxf(dn + g_reg*num, 1e-8f));
        }
        __syncthreads();
        // ---- fused filter update: fout = fbase - (step*alpha) * f_grad ----
        for (int i = tid; i < 8192; i += 288) {
            int c = i >> 6, rem = i & 63, py = rem >> 3, x4 = rem & 7;
            int gi = ((b*NC + c)*NH + y0 + py)*NW + x0 + x4*4;
            float4 fv4 = *(const float4*)(fbase + gi);
            float4 gv4 = *(const float4*)(fin + gi);     // fin == f_grad here
            float4 sa  = *(const float4*)(alphaS + py*32 + x4*4);
            float4 o;
            o.x = fv4.x - sa.x*gv4.x;
            o.y = fv4.y - sa.y*gv4.y;
            o.z = fv4.z - sa.z*gv4.z;
            o.w = fv4.w - sa.w*gv4.w;
            *(float4*)(fout + gi) = o;
        }
    }
}

// ---------------------------------------------------------------------------
// corr_t_kernel: f_grad(c,p) = reg*f(c,p) + sum_d mapped(d,p)*ref(c,p+d-4)
// 256 threads = 8 warps; warp cg handles 2 channels of a 16-channel chunk.
// mapped cached once in smem (pairs load free as u64); ref cp.async
// double-buffered (16-ch chunks). Inner loop in f32x2.
// Also writes alpha_num = sum_c f_grad^2 (in-block smem reduction).
// ---------------------------------------------------------------------------
#define CT_SMEM (45856*4 + 160*8)

__global__ __launch_bounds__(256)
void corr_t_kernel(const float* __restrict__ fin, const float* __restrict__ ref)
{
    extern __shared__ float sm[];
    float* mS = sm;                        // 81*8*36 = 23328 floats
    int2* tbl = (int2*)(sm + 45856);
    const int b  = blockIdx.z;
    const int x0 = blockIdx.x * TX, y0 = blockIdx.y * TY;
    const int tid = threadIdx.x;
    const int cg = tid >> 5;               // warp id 0..7
    const int r  = tid & 31;
    const int y  = r >> 2;
    const int xg = r & 3;
    const float regw = g_reg;

    build_ref_tbl(tbl, tid, 256, x0, y0);
    __syncthreads();

    const float* refb = ref + b*NC*NHW;

#define STAGE_CT(s, ch) do {                                                   \
        float* rb_ = sm + 23328 + (s)*11264;                                   \
        const float* rc_ = refb + (ch)*NHW;                                    \
        _Pragma("unroll")                                                      \
        for (int k_ = 0; k_ < 10; k_++) {                                      \
            int i_ = tid + k_*256;                                             \
            int c_ = div160(i_);                                               \
            int2 t_ = tbl[i_ - c_*160];                                        \
            bool v_ = (t_.x >= 0);                                             \
            const float* src_ = v_ ? (rc_ + c_*NHW + t_.x) : rc_;              \
            cpa16(rb_ + c_*704 + t_.y, src_, v_);                              \
        }                                                                      \
        cp_commit();                                                           \
    } while (0)

    STAGE_CT(0, 0);   // prefetch first ref chunk, overlaps with mS staging

    // stage mapped = grad_act * (act - v_plus*target) for all (d, pixel)
    for (int i = tid; i < ND*256; i += 256) {
        int d = i >> 8, p = i & 255, py = p >> 5, px = p & 31;
        float s = g_scores[((b*ND + d)*NH + y0 + py)*NW + x0 + px];
        float vp = g_vplus[d], alo = g_alo[d], ahi = g_ahi[d], tg = g_target[d];
        float sgn = (s > 0.f) ? 1.f : ((s < 0.f) ? -1.f : 0.f);
        float ga  = vp * (alo*sgn + ahi);
        float act = vp * (alo*fabsf(s) + ahi*s);
        mS[d*(TY*FST) + py*FST + px] = ga * (act - vp*tg);
    }

    float anum[8];
#pragma unroll
    for (int j = 0; j < 8; j++) anum[j] = 0.f;
    const int gh = y0 + y, gw = x0 + xg*8;

    for (int ci = 0; ci < 8; ci++) {
        if (ci < 7) { STAGE_CT((ci+1)&1, (ci+1)*16); cp_wait<1>(); }
        else        { cp_wait<0>(); }
        __syncthreads();
        const float* rbuf = sm + 23328 + (ci & 1)*11264;

        u64 acc2[2][4];
#pragma unroll
        for (int a = 0; a < 2; a++)
#pragma unroll
            for (int p = 0; p < 4; p++) acc2[a][p] = 0ull;

        for (int dyy = 0; dyy < 9; dyy++) {
            u64 mvp[9][4];
#pragma unroll
            for (int dx = 0; dx < 9; dx++) {
                const ulonglong2* mp = (const ulonglong2*)
                    (mS + (dyy*9 + dx)*(TY*FST) + y*FST + xg*8);
                ulonglong2 m0 = mp[0], m1 = mp[1];
                mvp[dx][0] = m0.x; mvp[dx][1] = m0.y;
                mvp[dx][2] = m1.x; mvp[dx][3] = m1.y;
            }
#pragma unroll
            for (int cl = 0; cl < 2; cl++) {
                const float4* rp = (const float4*)
                    (rbuf + (cg*2 + cl)*704 + (y + dyy)*RST + xg*8);
                float4 ra = rp[0], rb4 = rp[1], rc4 = rp[2], rd4 = rp[3];
                float rv[16] = {ra.x,ra.y,ra.z,ra.w, rb4.x,rb4.y,rb4.z,rb4.w,
                                rc4.x,rc4.y,rc4.z,rc4.w, rd4.x,rd4.y,rd4.z,rd4.w};
                u64 rvp[15];
#pragma unroll
                for (int k = 0; k < 15; k++) rvp[k] = pk2(rv[k], rv[k+1]);
#pragma unroll
                for (int dx = 0; dx < 9; dx++)
#pragma unroll
                    for (int p = 0; p < 4; p++)
                        acc2[cl][p] = fma2(mvp[dx][p], rvp[dx + 2*p], acc2[cl][p]);
            }
        }

        // finalize this chunk's 2 channels: add reg*f, write f_grad, alpha_num
#pragma unroll
        for (int cl = 0; cl < 2; cl++) {
            int c = ci*16 + cg*2 + cl;
            int gi = ((b*NC + c)*NH + gh)*NW + gw;
            float2 u0 = upk2(acc2[cl][0]), u1 = upk2(acc2[cl][1]);
            float2 u2 = upk2(acc2[cl][2]), u3 = upk2(acc2[cl][3]);
            float av[8] = {u0.x,u0.y,u1.x,u1.y, u2.x,u2.y,u3.x,u3.y};
            const float4* fp = (const float4*)(fin + gi);
            float4 fa = fp[0], fb4 = fp[1];
            float fv[8] = {fa.x,fa.y,fa.z,fa.w, fb4.x,fb4.y,fb4.z,fb4.w};
            float fg[8];
#pragma unroll
            for (int j = 0; j < 8; j++) fg[j] = fmaf(regw, fv[j], av[j]);
            float4* op = (float4*)(g_fgrad + gi);
            op[0] = make_float4(fg[0], fg[1], fg[2], fg[3]);
            op[1] = make_float4(fg[4], fg[5], fg[6], fg[7]);
#pragma unroll
            for (int j = 0; j < 8; j++) anum[j] = fmaf(fg[j], fg[j], anum[j]);
        }
        __syncthreads();
    }
#undef STAGE_CT

    // reduce alpha_num across the 8 warps (channels), write to global
    float* numS = sm;      // reuse mS region (all compute done)
    numS[tid] = 0.f;
    __syncthreads();
#pragma unroll
    for (int j = 0; j < 8; j++)
        atomicAdd(numS + (y*32 + xg*8 + j), anum[j]);
    __syncthreads();
    if (tid < 256)
        g_anum[b*NHW + (y0 + (tid >> 5))*NW + x0 + (tid & 31)] = numS[tid];
}

// ---------------------------------------------------------------------------
extern "C" void kernel_launch(void* const* d_in, const int* in_sizes, int n_in,
                              void* d_out, int out_size) {
    const float* fmap = (const float*)d_in[0];   // filter_map (b,c,H,W)
    const float* ref  = (const float*)d_in[1];   // reference_feat (b,c,H,W)
    const float* lw   = (const float*)d_in[2];   // label_w (10)
    const float* sw   = (const float*)d_in[3];   // spatial_w (10)
    const float* mw   = (const float*)d_in[4];   // mask_w (10)
    const float* ls   = (const float*)d_in[5];   // log_step_length (1)
    const float* fr   = (const float*)d_in[6];   // filter_reg (1)
    float* out = (float*)d_out;

    cudaFuncSetAttribute(corr_kernel<0>,
                         cudaFuncAttributeMaxDynamicSharedMemorySize, CORR_SMEM);
    cudaFuncSetAttribute(corr_kernel<1>,
                         cudaFuncAttributeMaxDynamicSharedMemorySize, CORR_SMEM);
    cudaFuncSetAttribute(corr_t_kernel,
                         cudaFuncAttributeMaxDynamicSharedMemorySize, CT_SMEM);

    void* p;
    cudaGetSymbolAddress(&p, g_f);     float* gf  = (float*)p;
    cudaGetSymbolAddress(&p, g_fgrad); float* gfg = (float*)p;

    setup_kernel<<<1, 128>>>(lw, sw, mw, ls, fr);

    dim3 grid(NW/TX, NH/TY, NB);   // (4, 16, 4)
    for (int it = 0; it < 3; it++) {
        const float* fin = (it == 0) ? fmap : gf;
        float* fout = (it == 2) ? out : gf;
        corr_kernel<0><<<grid, 288, CORR_SMEM>>>(fin, ref, nullptr, nullptr);  // scores
        corr_t_kernel<<<grid, 256, CT_SMEM>>>(fin, ref);           // f_grad + alpha_num
        corr_kernel<1><<<grid, 288, CORR_SMEM>>>(gfg, ref, fin, fout); // alpha_den + update
    }
}

// round 15
// speedup vs baseline: 1.0660x; 1.0625x over previous
#include <cuda_runtime.h>

// ---------------------------------------------------------------------------
// LocalGOCorrOpt: fused steepest-descent filter optimization.
// b=4, c=128, H=W=128, 9x9 search window (81 disps), 10 bins, 3 iterations.
// R14: scalar R11 base + 3-stage cp.async pipeline in corr kernels
// (4-channel chunks, 1 sync/chunk, ~2 chunks of latency slack per group).
// FFMA2 experiments reverted (regression). corr_t = R11 form.
// ---------------------------------------------------------------------------

#define NB 4
#define NC 128
#define NH 128
#define NW 128
#define NHW (NH*NW)
#define NS 9
#define ND 81
#define TX 32
#define TY 8
#define RST 44         // padded smem stride for ref window rows
#define FST 36         // padded smem stride for f / mapped rows

// ---------------- device scratch (no allocation allowed) -------------------
__device__ float g_scores[NB*ND*NHW];     // (b,81,H,W)
__device__ float g_fgrad[NB*NC*NHW];      // (b,c,H,W)
__device__ float g_f[NB*NC*NHW];          // current filter between iterations
__device__ float g_anum[NB*NHW];          // alpha numerator per pixel
__device__ float g_target[ND];
__device__ float g_vplus[ND];
__device__ float g_alo[ND];
__device__ float g_ahi[ND];
__device__ float g_step;
__device__ float g_reg;

// ---------------- per-displacement constants -------------------------------
__global__ void setup_kernel(const float* __restrict__ lw, const float* __restrict__ sw,
                             const float* __restrict__ mw, const float* __restrict__ ls,
                             const float* __restrict__ fr) {
    int d = threadIdx.x;
    if (d == 0) {
        g_step = expf(ls[0]);
        float rr = fr[0] * fr[0];
        g_reg = fmaxf(rr, 1e-10f) / (float)(NC * NC);
    }
    if (d < ND) {
        int dy = d / NS, dx = d % NS;
        float fy = (float)dy - 4.0f, fx = (float)dx - 4.0f;
        float dist = sqrtf(fy*fy + fx*fx) * 2.0f;   // / bin_displacement (0.5)
        float t = 0.f, vp = 0.f, m = 0.f;
        for (int k = 0; k < 10; k++) {
            float val;
            if (k == 9) val = fminf(fmaxf(dist - 8.0f, 0.0f), 1.0f);
            else        val = fmaxf(1.0f - fabsf(dist - (float)k), 0.0f);
            t  += val * lw[k];
            vp += val * sw[k];
            m  += val * mw[k];
        }
        float wm = 1.0f / (1.0f + expf(-m));        // sigmoid
        g_target[d] = t;
        g_vplus[d]  = vp;
        g_alo[d]    = (1.0f - wm) * 0.5f;
        g_ahi[d]    = (1.0f + wm) * 0.5f;
    }
}

// ---------------- cp.async helpers -----------------------------------------
__device__ __forceinline__ void cpa16(float* dst, const float* src, bool v) {
    unsigned s = (unsigned)__cvta_generic_to_shared(dst);
    int n = v ? 16 : 0;                  // src-size 0 -> zero-fill destination
    asm volatile("cp.async.cg.shared.global [%0], [%1], 16, %2;\n"
                 :: "r"(s), "l"(src), "r"(n));
}
__device__ __forceinline__ void cp_commit() {
    asm volatile("cp.async.commit_group;\n");
}
template<int N> __device__ __forceinline__ void cp_wait() {
    asm volatile("cp.async.wait_group %0;\n" :: "n"(N));
}
// i / 160 for 0 <= i < 4096
__device__ __forceinline__ int div160(int i) {
    return (int)(((unsigned)i * 52429u) >> 23);
}

// Build per-block ref-window staging table: for each of the 160 float4 slots
// of one channel's window: x = global spatial offset (or -1 if OOB zero-fill),
// y = smem offset within the channel's 704-float region.
__device__ __forceinline__ void build_ref_tbl(int2* tbl, int tid, int nthr,
                                              int x0, int y0) {
    for (int i = tid; i < 160; i += nthr) {
        int wy = i / 10, wx4 = i - wy*10;
        int h = y0 + wy - 4, w = x0 + wx4*4 - 4;
        bool v = ((unsigned)h < NH) && ((unsigned)w < NW);
        tbl[i] = make_int2(v ? (h*NW + w) : -1, wy*RST + wx4*4);
    }
}

// ---------------------------------------------------------------------------
// corr_kernel: scores(p,d) = sum_c f(c,p) * ref(c, p+d-4)
// 288 threads = 9 warps; warp w handles dy=w; thread tile = 8 px (x) * 9 dx.
// Channels streamed in 4-ch chunks through a 3-stage cp.async pipeline:
//   prologue stages g0,g1; loop: wait(<=1) -> sync -> stage(k+2) -> compute(k)
// One __syncthreads per chunk; ~2 chunks of latency slack per group.
// MODE 0: write g_scores.
// MODE 1: fin = f_grad; epilogue reduces alpha_den in smem, computes alpha,
//         and applies the filter update (fout = fbase - step*alpha*f_grad).
// Buffer: rS 4*704=2816 + fS 4*288=1152 = 3968 floats; 3 stages.
// ---------------------------------------------------------------------------
#define CBUF 3968
#define CORR_SMEM (3*CBUF*4 + 160*8)   // 47616 + 1280 = 48896 B

template<int MODE>
__global__ __launch_bounds__(288, 2)
void corr_kernel(const float* __restrict__ fin, const float* __restrict__ ref,
                 const float* __restrict__ fbase, float* __restrict__ fout)
{
    extern __shared__ float sm[];
    int2* tbl = (int2*)(sm + 3*CBUF);
    const int b  = blockIdx.z;
    const int x0 = blockIdx.x * TX, y0 = blockIdx.y * TY;
    const int tid = threadIdx.x;
    const int dy = tid >> 5;
    const int r  = tid & 31;
    const int y  = r >> 2;
    const int xg = r & 3;

    build_ref_tbl(tbl, tid, 288, x0, y0);

    const float* refb = ref + b*NC*NHW;
    const float* finb = fin + ((b*NC)*NH + y0)*NW + x0;

    float acc[9][8];
#pragma unroll
    for (int a = 0; a < 9; a++)
#pragma unroll
        for (int j = 0; j < 8; j++) acc[a][j] = 0.f;

    // Stage 4 channels (ch..ch+3) into buffer s.
#define STAGE_CORR(s, ch) do {                                                 \
        float* rb_ = sm + (s)*CBUF;                                            \
        float* fb_ = rb_ + 2816;                                               \
        const float* rc_ = refb + (ch)*NHW;                                    \
        _Pragma("unroll")                                                      \
        for (int k_ = 0; k_ < 3; k_++) {                                       \
            int i_ = tid + k_*288;                                             \
            if (i_ < 640) {                                                    \
                int c_ = div160(i_);                                           \
                int2 t_ = tbl[i_ - c_*160];                                    \
                bool v_ = (t_.x >= 0);                                         \
                const float* src_ = v_ ? (rc_ + c_*NHW + t_.x) : rc_;          \
                cpa16(rb_ + c_*704 + t_.y, src_, v_);                          \
            }                                                                  \
        }                                                                      \
        if (tid < 256) {                                                       \
            int c_ = tid >> 6, rem_ = tid & 63;                                \
            int yy_ = rem_ >> 3, x4_ = rem_ & 7;                               \
            cpa16(fb_ + c_*288 + yy_*36 + x4_*4,                               \
                  finb + ((ch) + c_)*NHW + yy_*NW + x4_*4, true);              \
        }                                                                      \
        cp_commit();                                                           \
    } while (0)

    __syncthreads();      // table ready before staging reads it
    STAGE_CORR(0, 0);
    STAGE_CORR(1, 4);

    int bc = 0;           // compute buffer index (ci % 3)
    int bsg = 2;          // next staging buffer index ((ci+2) % 3)
    for (int ci = 0; ci < 32; ci++) {
        if (ci < 31) cp_wait<1>(); else cp_wait<0>();
        __syncthreads();  // group ci arrived everywhere; compute(ci-1) done
        if (ci < 30) {
            STAGE_CORR(bsg, (ci + 2)*4);
            bsg = (bsg == 2) ? 0 : bsg + 1;
        }
        const float* rbuf = sm + bc*CBUF;
        const float* fbuf = rbuf + 2816;
#pragma unroll
        for (int cl = 0; cl < 4; cl++) {
            const float4* rp = (const float4*)(rbuf + cl*704 + (y+dy)*RST + xg*8);
            float4 ra = rp[0], rb4 = rp[1], rc4 = rp[2], rd4 = rp[3];
            float rv[16] = {ra.x,ra.y,ra.z,ra.w, rb4.x,rb4.y,rb4.z,rb4.w,
                            rc4.x,rc4.y,rc4.z,rc4.w, rd4.x,rd4.y,rd4.z,rd4.w};
            const float4* fp = (const float4*)(fbuf + cl*288 + y*36 + xg*8);
            float4 fa = fp[0], fb4 = fp[1];
            float fv[8] = {fa.x,fa.y,fa.z,fa.w, fb4.x,fb4.y,fb4.z,fb4.w};
#pragma unroll
            for (int dx = 0; dx < 9; dx++)
#pragma unroll
                for (int j = 0; j < 8; j++)
                    acc[dx][j] = fmaf(fv[j], rv[dx + j], acc[dx][j]);
        }
        bc = (bc == 2) ? 0 : bc + 1;
    }
#undef STAGE_CORR

    const int gh = y0 + y, gw = x0 + xg*8;
    if (MODE == 0) {
#pragma unroll
        for (int dx = 0; dx < 9; dx++) {
            int d = dy*9 + dx;
            float4* outp = (float4*)(g_scores + ((b*ND + d)*NH + gh)*NW + gw);
            outp[0] = make_float4(acc[dx][0], acc[dx][1], acc[dx][2], acc[dx][3]);
            outp[1] = make_float4(acc[dx][4], acc[dx][5], acc[dx][6], acc[dx][7]);
        }
    } else {
        // ---- alpha_den = sum_d sg^2, reduced across the 9 dy-warps --------
        float den[8];
#pragma unroll
        for (int j = 0; j < 8; j++) den[j] = 0.f;
#pragma unroll
        for (int dx = 0; dx < 9; dx++) {
            int d = dy*9 + dx;
            float vp = g_vplus[d], alo = g_alo[d], ahi = g_ahi[d];
            const float4* sp = (const float4*)(g_scores + ((b*ND + d)*NH + gh)*NW + gw);
            float4 sa = sp[0], sb = sp[1];
            float sv[8] = {sa.x,sa.y,sa.z,sa.w, sb.x,sb.y,sb.z,sb.w};
#pragma unroll
            for (int j = 0; j < 8; j++) {
                float s = sv[j];
                float sgn = (s > 0.f) ? 1.f : ((s < 0.f) ? -1.f : 0.f);
                float ga = vp * (alo*sgn + ahi);         // grad_act
                float sg = ga * acc[dx][j];
                den[j] = fmaf(sg, sg, den[j]);
            }
        }
        float* denS   = sm;        // reuse staging smem
        float* alphaS = sm + 256;
        __syncthreads();
        if (tid < 256) denS[tid] = 0.f;
        __syncthreads();
#pragma unroll
        for (int j = 0; j < 8; j++)
            atomicAdd(denS + (y*32 + xg*8 + j), den[j]);
        __syncthreads();
        if (tid < 256) {
            int py = tid >> 5, px = tid & 31;
            float num = g_anum[b*NHW + (y0 + py)*NW + x0 + px];
            float dn  = denS[tid];
            alphaS[tid] = g_step * (num / fmaxf(dn + g_reg*num, 1e-8f));
        }
        __syncthreads();
        // ---- fused filter update: fout = fbase - (step*alpha) * f_grad ----
        for (int i = tid; i < 8192; i += 288) {
            int c = i >> 6, rem = i & 63, py = rem >> 3, x4 = rem & 7;
            int gi = ((b*NC + c)*NH + y0 + py)*NW + x0 + x4*4;
            float4 fv4 = *(const float4*)(fbase + gi);
            float4 gv4 = *(const float4*)(fin + gi);     // fin == f_grad here
            float4 sa  = *(const float4*)(alphaS + py*32 + x4*4);
            float4 o;
            o.x = fv4.x - sa.x*gv4.x;
            o.y = fv4.y - sa.y*gv4.y;
            o.z = fv4.z - sa.z*gv4.z;
            o.w = fv4.w - sa.w*gv4.w;
            *(float4*)(fout + gi) = o;
        }
    }
}

// ---------------------------------------------------------------------------
// corr_t_kernel: f_grad(c,p) = reg*f(c,p) + sum_d mapped(d,p)*ref(c,p+d-4)
// (R11 form) 128 threads = 4 warps; warp cg handles 4 channels of a
// 16-channel chunk. mapped cached once in smem; ref cp.async double-buffered.
// Also writes alpha_num = sum_c f_grad^2 (in-block smem reduction).
// Dynamic smem: (23328 + 2*11264) floats + 160 int2 = 184704 B.
// ---------------------------------------------------------------------------
#define CT_SMEM (45856*4 + 160*8)

__global__ __launch_bounds__(128)
void corr_t_kernel(const float* __restrict__ fin, const float* __restrict__ ref)
{
    extern __shared__ float sm[];
    float* mS = sm;                        // 81*8*36 = 23328 floats
    int2* tbl = (int2*)(sm + 45856);
    const int b  = blockIdx.z;
    const int x0 = blockIdx.x * TX, y0 = blockIdx.y * TY;
    const int tid = threadIdx.x;
    const int cg = tid >> 5;
    const int r  = tid & 31;
    const int y  = r >> 2;
    const int xg = r & 3;
    const float regw = g_reg;

    build_ref_tbl(tbl, tid, 128, x0, y0);
    __syncthreads();

    const float* refb = ref + b*NC*NHW;

#define STAGE_CT(s, ch) do {                                                   \
        float* rb_ = sm + 23328 + (s)*11264;                                   \
        const float* rc_ = refb + (ch)*NHW;                                    \
        _Pragma("unroll")                                                      \
        for (int k_ = 0; k_ < 20; k_++) {                                      \
            int i_ = tid + k_*128;                                             \
            int c_ = div160(i_);                                               \
            int2 t_ = tbl[i_ - c_*160];                                        \
            bool v_ = (t_.x >= 0);                                             \
            const float* src_ = v_ ? (rc_ + c_*NHW + t_.x) : rc_;              \
            cpa16(rb_ + c_*704 + t_.y, src_, v_);                              \
        }                                                                      \
        cp_commit();                                                           \
    } while (0)

    STAGE_CT(0, 0);   // prefetch first ref chunk, overlaps with mS staging

    // stage mapped = grad_act * (act - v_plus*target) for all (d, pixel)
    for (int i = tid; i < ND*256; i += 128) {
        int d = i >> 8, p = i & 255, py = p >> 5, px = p & 31;
        float s = g_scores[((b*ND + d)*NH + y0 + py)*NW + x0 + px];
        float vp = g_vplus[d], alo = g_alo[d], ahi = g_ahi[d], tg = g_target[d];
        float sgn = (s > 0.f) ? 1.f : ((s < 0.f) ? -1.f : 0.f);
        float ga  = vp * (alo*sgn + ahi);
        float act = vp * (alo*fabsf(s) + ahi*s);
        mS[d*(TY*FST) + py*FST + px] = ga * (act - vp*tg);
    }

    float anum[8];
#pragma unroll
    for (int j = 0; j < 8; j++) anum[j] = 0.f;
    const int gh = y0 + y, gw = x0 + xg*8;

    for (int ci = 0; ci < 8; ci++) {
        if (ci < 7) { STAGE_CT((ci+1)&1, (ci+1)*16); cp_wait<1>(); }
        else        { cp_wait<0>(); }
        __syncthreads();
        const float* rbuf = sm + 23328 + (ci & 1)*11264;

        float acc[4][8];
#pragma unroll
        for (int a = 0; a < 4; a++)
#pragma unroll
            for (int j = 0; j < 8; j++) acc[a][j] = 0.f;

        for (int dyy = 0; dyy < 9; dyy++) {
            float mv[9][8];
#pragma unroll
            for (int dx = 0; dx < 9; dx++) {
                const float4* mp = (const float4*)(mS + (dyy*9 + dx)*(TY*FST) + y*FST + xg*8);
                float4 m0 = mp[0], m1 = mp[1];
                mv[dx][0]=m0.x; mv[dx][1]=m0.y; mv[dx][2]=m0.z; mv[dx][3]=m0.w;
                mv[dx][4]=m1.x; mv[dx][5]=m1.y; mv[dx][6]=m1.z; mv[dx][7]=m1.w;
            }
#pragma unroll
            for (int cl = 0; cl < 4; cl++) {
                const float4* rp = (const float4*)(rbuf + (cg*4 + cl)*704 + (y + dyy)*RST + xg*8);
                float4 ra = rp[0], rb4 = rp[1], rc4 = rp[2], rd4 = rp[3];
                float rv[16] = {ra.x,ra.y,ra.z,ra.w, rb4.x,rb4.y,rb4.z,rb4.w,
                                rc4.x,rc4.y,rc4.z,rc4.w, rd4.x,rd4.y,rd4.z,rd4.w};
#pragma unroll
                for (int dx = 0; dx < 9; dx++)
#pragma unroll
                    for (int j = 0; j < 8; j++)
                        acc[cl][j] = fmaf(mv[dx][j], rv[dx + j], acc[cl][j]);
            }
        }

        // finalize this chunk's 4 channels: add reg*f, write f_grad, alpha_num
#pragma unroll
        for (int cl = 0; cl < 4; cl++) {
            int c = ci*16 + cg*4 + cl;
            int gi = ((b*NC + c)*NH + gh)*NW + gw;
            const float4* fp = (const float4*)(fin + gi);
            float4 fa = fp[0], fb4 = fp[1];
            float fg[8];
            fg[0] = fmaf(regw, fa.x, acc[cl][0]);
            fg[1] = fmaf(regw, fa.y, acc[cl][1]);
            fg[2] = fmaf(regw, fa.z, acc[cl][2]);
            fg[3] = fmaf(regw, fa.w, acc[cl][3]);
            fg[4] = fmaf(regw, fb4.x, acc[cl][4]);
            fg[5] = fmaf(regw, fb4.y, acc[cl][5]);
            fg[6] = fmaf(regw, fb4.z, acc[cl][6]);
            fg[7] = fmaf(regw, fb4.w, acc[cl][7]);
            float4* op = (float4*)(g_fgrad + gi);
            op[0] = make_float4(fg[0], fg[1], fg[2], fg[3]);
            op[1] = make_float4(fg[4], fg[5], fg[6], fg[7]);
#pragma unroll
            for (int j = 0; j < 8; j++) anum[j] = fmaf(fg[j], fg[j], anum[j]);
        }
        __syncthreads();
    }
#undef STAGE_CT

    // reduce alpha_num across the 4 warps (channels), write to global
    float* numS = sm;      // reuse mS region (all compute done)
    numS[tid] = 0.f; numS[tid + 128] = 0.f;
    __syncthreads();
#pragma unroll
    for (int j = 0; j < 8; j++)
        atomicAdd(numS + (y*32 + xg*8 + j), anum[j]);
    __syncthreads();
    for (int i = tid; i < 256; i += 128)
        g_anum[b*NHW + (y0 + (i >> 5))*NW + x0 + (i & 31)] = numS[i];
}

// ---------------------------------------------------------------------------
extern "C" void kernel_launch(void* const* d_in, const int* in_sizes, int n_in,
                              void* d_out, int out_size) {
    const float* fmap = (const float*)d_in[0];   // filter_map (b,c,H,W)
    const float* ref  = (const float*)d_in[1];   // reference_feat (b,c,H,W)
    const float* lw   = (const float*)d_in[2];   // label_w (10)
    const float* sw   = (const float*)d_in[3];   // spatial_w (10)
    const float* mw   = (const float*)d_in[4];   // mask_w (10)
    const float* ls   = (const float*)d_in[5];   // log_step_length (1)
    const float* fr   = (const float*)d_in[6];   // filter_reg (1)
    float* out = (float*)d_out;

    cudaFuncSetAttribute(corr_kernel<0>,
                         cudaFuncAttributeMaxDynamicSharedMemorySize, CORR_SMEM);
    cudaFuncSetAttribute(corr_kernel<1>,
                         cudaFuncAttributeMaxDynamicSharedMemorySize, CORR_SMEM);
    cudaFuncSetAttribute(corr_t_kernel,
                         cudaFuncAttributeMaxDynamicSharedMemorySize, CT_SMEM);

    void* p;
    cudaGetSymbolAddress(&p, g_f);     float* gf  = (float*)p;
    cudaGetSymbolAddress(&p, g_fgrad); float* gfg = (float*)p;

    setup_kernel<<<1, 128>>>(lw, sw, mw, ls, fr);

    dim3 grid(NW/TX, NH/TY, NB);   // (4, 16, 4)
    for (int it = 0; it < 3; it++) {
        const float* fin = (it == 0) ? fmap : gf;
        float* fout = (it == 2) ? out : gf;
        corr_kernel<0><<<grid, 288, CORR_SMEM>>>(fin, ref, nullptr, nullptr);  // scores
        corr_t_kernel<<<grid, 128, CT_SMEM>>>(fin, ref);           // f_grad + alpha_num
        corr_kernel<1><<<grid, 288, CORR_SMEM>>>(gfg, ref, fin, fout); // alpha_den + update
    }
}

// round 16
// speedup vs baseline: 1.1859x; 1.1125x over previous
#include <cuda_runtime.h>

// ---------------------------------------------------------------------------
// LocalGOCorrOpt: fused steepest-descent filter optimization.
// b=4, c=128, H=W=128, 9x9 search window (81 disps), 10 bins, 3 iterations.
// R16: corr kernels -> 3-stage cp.async pipeline with 8-channel chunks
// (16 syncs, ~2 chunks slack) + dedicated producer warp (320 threads:
// 9 compute warps + 1 staging warp). corr_t = R11 form (best measured).
// ---------------------------------------------------------------------------

#define NB 4
#define NC 128
#define NH 128
#define NW 128
#define NHW (NH*NW)
#define NS 9
#define ND 81
#define TX 32
#define TY 8
#define RST 44         // padded smem stride for ref window rows
#define FST 36         // padded smem stride for f / mapped rows

// ---------------- device scratch (no allocation allowed) -------------------
__device__ float g_scores[NB*ND*NHW];     // (b,81,H,W)
__device__ float g_fgrad[NB*NC*NHW];      // (b,c,H,W)
__device__ float g_f[NB*NC*NHW];          // current filter between iterations
__device__ float g_anum[NB*NHW];          // alpha numerator per pixel
__device__ float g_target[ND];
__device__ float g_vplus[ND];
__device__ float g_alo[ND];
__device__ float g_ahi[ND];
__device__ float g_step;
__device__ float g_reg;

// ---------------- per-displacement constants -------------------------------
__global__ void setup_kernel(const float* __restrict__ lw, const float* __restrict__ sw,
                             const float* __restrict__ mw, const float* __restrict__ ls,
                             const float* __restrict__ fr) {
    int d = threadIdx.x;
    if (d == 0) {
        g_step = expf(ls[0]);
        float rr = fr[0] * fr[0];
        g_reg = fmaxf(rr, 1e-10f) / (float)(NC * NC);
    }
    if (d < ND) {
        int dy = d / NS, dx = d % NS;
        float fy = (float)dy - 4.0f, fx = (float)dx - 4.0f;
        float dist = sqrtf(fy*fy + fx*fx) * 2.0f;   // / bin_displacement (0.5)
        float t = 0.f, vp = 0.f, m = 0.f;
        for (int k = 0; k < 10; k++) {
            float val;
            if (k == 9) val = fminf(fmaxf(dist - 8.0f, 0.0f), 1.0f);
            else        val = fmaxf(1.0f - fabsf(dist - (float)k), 0.0f);
            t  += val * lw[k];
            vp += val * sw[k];
            m  += val * mw[k];
        }
        float wm = 1.0f / (1.0f + expf(-m));        // sigmoid
        g_target[d] = t;
        g_vplus[d]  = vp;
        g_alo[d]    = (1.0f - wm) * 0.5f;
        g_ahi[d]    = (1.0f + wm) * 0.5f;
    }
}

// ---------------- cp.async helpers -----------------------------------------
__device__ __forceinline__ void cpa16(float* dst, const float* src, bool v) {
    unsigned s = (unsigned)__cvta_generic_to_shared(dst);
    int n = v ? 16 : 0;                  // src-size 0 -> zero-fill destination
    asm volatile("cp.async.cg.shared.global [%0], [%1], 16, %2;\n"
                 :: "r"(s), "l"(src), "r"(n));
}
__device__ __forceinline__ void cp_commit() {
    asm volatile("cp.async.commit_group;\n");
}
template<int N> __device__ __forceinline__ void cp_wait() {
    asm volatile("cp.async.wait_group %0;\n" :: "n"(N));
}
// i / 160 for 0 <= i < 4096
__device__ __forceinline__ int div160(int i) {
    return (int)(((unsigned)i * 52429u) >> 23);
}

// Build per-block ref-window staging table: for each of the 160 float4 slots
// of one channel's window: x = global spatial offset (or -1 if OOB zero-fill),
// y = smem offset within the channel's 704-float region.
__device__ __forceinline__ void build_ref_tbl(int2* tbl, int tid, int nthr,
                                              int x0, int y0) {
    for (int i = tid; i < 160; i += nthr) {
        int wy = i / 10, wx4 = i - wy*10;
        int h = y0 + wy - 4, w = x0 + wx4*4 - 4;
        bool v = ((unsigned)h < NH) && ((unsigned)w < NW);
        tbl[i] = make_int2(v ? (h*NW + w) : -1, wy*RST + wx4*4);
    }
}

// ---------------------------------------------------------------------------
// corr_kernel: scores(p,d) = sum_c f(c,p) * ref(c, p+d-4)
// 320 threads: warps 0-8 compute (warp w <-> dy=w, thread tile 8px x 9dx);
// warp 9 is a dedicated PRODUCER that does all cp.async staging.
// Channels streamed in 8-ch chunks through a 3-stage pipeline (16 syncs,
// ~2 chunks of in-flight slack). Only the producer commits/waits cp.async
// groups; __syncthreads publishes the data to consumers.
// MODE 0: write g_scores.
// MODE 1: fin = f_grad; epilogue reduces alpha_den in smem, computes alpha,
//         and applies the filter update (fout = fbase - step*alpha*f_grad).
// Buffer: rS 8*704=5632 + fS 8*288=2304 = 7936 floats; 3 stages.
// ---------------------------------------------------------------------------
#define CBUF 7936
#define CORR_SMEM (3*CBUF*4 + 160*8)   // 95232 + 1280 = 96512 B

template<int MODE>
__global__ __launch_bounds__(320, 2)
void corr_kernel(const float* __restrict__ fin, const float* __restrict__ ref,
                 const float* __restrict__ fbase, float* __restrict__ fout)
{
    extern __shared__ float sm[];
    int2* tbl = (int2*)(sm + 3*CBUF);
    const int b  = blockIdx.z;
    const int x0 = blockIdx.x * TX, y0 = blockIdx.y * TY;
    const int tid = threadIdx.x;
    const int dy = tid >> 5;               // 0..8 compute, 9 producer
    const int r  = tid & 31;
    const int y  = r >> 2;
    const int xg = r & 3;
    const bool producer = (dy == 9);

    build_ref_tbl(tbl, tid, 320, x0, y0);
    __syncthreads();                       // table ready

    const float* refb = ref + b*NC*NHW;
    const float* finb = fin + ((b*NC)*NH + y0)*NW + x0;

    float acc[9][8];
#pragma unroll
    for (int a = 0; a < 9; a++)
#pragma unroll
        for (int j = 0; j < 8; j++) acc[a][j] = 0.f;

    if (producer) {
        // ---- staging-only warp: 16 groups of 8 channels, 3-stage ring ----
        const int lane = r;
        auto stage = [&](int s, int ch) {
            float* rb_ = sm + s*CBUF;
            float* fb_ = rb_ + 5632;
            const float* rc_ = refb + ch*NHW;
            for (int i = lane; i < 1280; i += 32) {
                int c_ = div160(i);
                int2 t_ = tbl[i - c_*160];
                bool v_ = (t_.x >= 0);
                const float* src_ = v_ ? (rc_ + c_*NHW + t_.x) : rc_;
                cpa16(rb_ + c_*704 + t_.y, src_, v_);
            }
            for (int i = lane; i < 512; i += 32) {
                int c_ = i >> 6, rem_ = i & 63;
                int yy_ = rem_ >> 3, x4_ = rem_ & 7;
                cpa16(fb_ + c_*288 + yy_*36 + x4_*4,
                      finb + (ch + c_)*NHW + yy_*NW + x4_*4, true);
            }
            cp_commit();
        };
        stage(0, 0);
        stage(1, 8);
        int bsg = 2;
        for (int ci = 0; ci < 16; ci++) {
            if (ci < 15) cp_wait<1>(); else cp_wait<0>();  // group ci landed
            __syncthreads();                               // publish to consumers
            if (ci < 14) {
                stage(bsg, (ci + 2)*8);
                bsg = (bsg == 2) ? 0 : bsg + 1;
            }
        }
    } else {
        // ---- compute warps: consume buffers in ring order ----
        int bc = 0;
        for (int ci = 0; ci < 16; ci++) {
            __syncthreads();               // wait for producer's group ci
#pragma unroll
            for (int cl = 0; cl < 8; cl++) {
                const float* rbuf = sm + bc*CBUF;
                const float* fbuf = rbuf + 5632;
                const float4* rp = (const float4*)(rbuf + cl*704 + (y+dy)*RST + xg*8);
                float4 ra = rp[0], rb4 = rp[1], rc4 = rp[2], rd4 = rp[3];
                float rv[16] = {ra.x,ra.y,ra.z,ra.w, rb4.x,rb4.y,rb4.z,rb4.w,
                                rc4.x,rc4.y,rc4.z,rc4.w, rd4.x,rd4.y,rd4.z,rd4.w};
                const float4* fp = (const float4*)(fbuf + cl*288 + y*36 + xg*8);
                float4 fa = fp[0], fb4 = fp[1];
                float fv[8] = {fa.x,fa.y,fa.z,fa.w, fb4.x,fb4.y,fb4.z,fb4.w};
#pragma unroll
                for (int dx = 0; dx < 9; dx++)
#pragma unroll
                    for (int j = 0; j < 8; j++)
                        acc[dx][j] = fmaf(fv[j], rv[dx + j], acc[dx][j]);
            }
            bc = (bc == 2) ? 0 : bc + 1;
        }
    }

    const int gh = y0 + y, gw = x0 + xg*8;
    if (MODE == 0) {
        if (!producer) {
#pragma unroll
            for (int dx = 0; dx < 9; dx++) {
                int d = dy*9 + dx;
                float4* outp = (float4*)(g_scores + ((b*ND + d)*NH + gh)*NW + gw);
                outp[0] = make_float4(acc[dx][0], acc[dx][1], acc[dx][2], acc[dx][3]);
                outp[1] = make_float4(acc[dx][4], acc[dx][5], acc[dx][6], acc[dx][7]);
            }
        }
    } else {
        // ---- alpha_den = sum_d sg^2, reduced across the 9 dy-warps --------
        float den[8];
#pragma unroll
        for (int j = 0; j < 8; j++) den[j] = 0.f;
        if (!producer) {
#pragma unroll
            for (int dx = 0; dx < 9; dx++) {
                int d = dy*9 + dx;
                float vp = g_vplus[d], alo = g_alo[d], ahi = g_ahi[d];
                const float4* sp = (const float4*)(g_scores + ((b*ND + d)*NH + gh)*NW + gw);
                float4 sa = sp[0], sb = sp[1];
                float sv[8] = {sa.x,sa.y,sa.z,sa.w, sb.x,sb.y,sb.z,sb.w};
#pragma unroll
                for (int j = 0; j < 8; j++) {
                    float s = sv[j];
                    float sgn = (s > 0.f) ? 1.f : ((s < 0.f) ? -1.f : 0.f);
                    float ga = vp * (alo*sgn + ahi);         // grad_act
                    float sg = ga * acc[dx][j];
                    den[j] = fmaf(sg, sg, den[j]);
                }
            }
        }
        float* denS   = sm;        // reuse staging smem
        float* alphaS = sm + 256;
        __syncthreads();
        if (tid < 256) denS[tid] = 0.f;
        __syncthreads();
        if (!producer) {
#pragma unroll
            for (int j = 0; j < 8; j++)
                atomicAdd(denS + (y*32 + xg*8 + j), den[j]);
        }
        __syncthreads();
        if (tid < 256) {
            int py = tid >> 5, px = tid & 31;
            float num = g_anum[b*NHW + (y0 + py)*NW + x0 + px];
            float dn  = denS[tid];
            alphaS[tid] = g_step * (num / fmaxf(dn + g_reg*num, 1e-8f));
        }
        __syncthreads();
        // ---- fused filter update: fout = fbase - (step*alpha) * f_grad ----
        for (int i = tid; i < 8192; i += 320) {
            int c = i >> 6, rem = i & 63, py = rem >> 3, x4 = rem & 7;
            int gi = ((b*NC + c)*NH + y0 + py)*NW + x0 + x4*4;
            float4 fv4 = *(const float4*)(fbase + gi);
            float4 gv4 = *(const float4*)(fin + gi);     // fin == f_grad here
            float4 sa  = *(const float4*)(alphaS + py*32 + x4*4);
            float4 o;
            o.x = fv4.x - sa.x*gv4.x;
            o.y = fv4.y - sa.y*gv4.y;
            o.z = fv4.z - sa.z*gv4.z;
            o.w = fv4.w - sa.w*gv4.w;
            *(float4*)(fout + gi) = o;
        }
    }
}

// ---------------------------------------------------------------------------
// corr_t_kernel: f_grad(c,p) = reg*f(c,p) + sum_d mapped(d,p)*ref(c,p+d-4)
// (R11 form) 128 threads = 4 warps; warp cg handles 4 channels of a
// 16-channel chunk. mapped cached once in smem; ref cp.async double-buffered.
// Also writes alpha_num = sum_c f_grad^2 (in-block smem reduction).
// Dynamic smem: (23328 + 2*11264) floats + 160 int2 = 184704 B.
// ---------------------------------------------------------------------------
#define CT_SMEM (45856*4 + 160*8)

__global__ __launch_bounds__(128)
void corr_t_kernel(const float* __restrict__ fin, const float* __restrict__ ref)
{
    extern __shared__ float sm[];
    float* mS = sm;                        // 81*8*36 = 23328 floats
    int2* tbl = (int2*)(sm + 45856);
    const int b  = blockIdx.z;
    const int x0 = blockIdx.x * TX, y0 = blockIdx.y * TY;
    const int tid = threadIdx.x;
    const int cg = tid >> 5;
    const int r  = tid & 31;
    const int y  = r >> 2;
    const int xg = r & 3;
    const float regw = g_reg;

    build_ref_tbl(tbl, tid, 128, x0, y0);
    __syncthreads();

    const float* refb = ref + b*NC*NHW;

#define STAGE_CT(s, ch) do {                                                   \
        float* rb_ = sm + 23328 + (s)*11264;                                   \
        const float* rc_ = refb + (ch)*NHW;                                    \
        _Pragma("unroll")                                                      \
        for (int k_ = 0; k_ < 20; k_++) {                                      \
            int i_ = tid + k_*128;                                             \
            int c_ = div160(i_);                                               \
            int2 t_ = tbl[i_ - c_*160];                                        \
            bool v_ = (t_.x >= 0);                                             \
            const float* src_ = v_ ? (rc_ + c_*NHW + t_.x) : rc_;              \
            cpa16(rb_ + c_*704 + t_.y, src_, v_);                              \
        }                                                                      \
        cp_commit();                                                           \
    } while (0)

    STAGE_CT(0, 0);   // prefetch first ref chunk, overlaps with mS staging

    // stage mapped = grad_act * (act - v_plus*target) for all (d, pixel)
    for (int i = tid; i < ND*256; i += 128) {
        int d = i >> 8, p = i & 255, py = p >> 5, px = p & 31;
        float s = g_scores[((b*ND + d)*NH + y0 + py)*NW + x0 + px];
        float vp = g_vplus[d], alo = g_alo[d], ahi = g_ahi[d], tg = g_target[d];
        float sgn = (s > 0.f) ? 1.f : ((s < 0.f) ? -1.f : 0.f);
        float ga  = vp * (alo*sgn + ahi);
        float act = vp * (alo*fabsf(s) + ahi*s);
        mS[d*(TY*FST) + py*FST + px] = ga * (act - vp*tg);
    }

    float anum[8];
#pragma unroll
    for (int j = 0; j < 8; j++) anum[j] = 0.f;
    const int gh = y0 + y, gw = x0 + xg*8;

    for (int ci = 0; ci < 8; ci++) {
        if (ci < 7) { STAGE_CT((ci+1)&1, (ci+1)*16); cp_wait<1>(); }
        else        { cp_wait<0>(); }
        __syncthreads();
        const float* rbuf = sm + 23328 + (ci & 1)*11264;

        float acc[4][8];
#pragma unroll
        for (int a = 0; a < 4; a++)
#pragma unroll
            for (int j = 0; j < 8; j++) acc[a][j] = 0.f;

        for (int dyy = 0; dyy < 9; dyy++) {
            float mv[9][8];
#pragma unroll
            for (int dx = 0; dx < 9; dx++) {
                const float4* mp = (const float4*)(mS + (dyy*9 + dx)*(TY*FST) + y*FST + xg*8);
                float4 m0 = mp[0], m1 = mp[1];
                mv[dx][0]=m0.x; mv[dx][1]=m0.y; mv[dx][2]=m0.z; mv[dx][3]=m0.w;
                mv[dx][4]=m1.x; mv[dx][5]=m1.y; mv[dx][6]=m1.z; mv[dx][7]=m1.w;
            }
#pragma unroll
            for (int cl = 0; cl < 4; cl++) {
                const float4* rp = (const float4*)(rbuf + (cg*4 + cl)*704 + (y + dyy)*RST + xg*8);
                float4 ra = rp[0], rb4 = rp[1], rc4 = rp[2], rd4 = rp[3];
                float rv[16] = {ra.x,ra.y,ra.z,ra.w, rb4.x,rb4.y,rb4.z,rb4.w,
                                rc4.x,rc4.y,rc4.z,rc4.w, rd4.x,rd4.y,rd4.z,rd4.w};
#pragma unroll
                for (int dx = 0; dx < 9; dx++)
#pragma unroll
                    for (int j = 0; j < 8; j++)
                        acc[cl][j] = fmaf(mv[dx][j], rv[dx + j], acc[cl][j]);
            }
        }

        // finalize this chunk's 4 channels: add reg*f, write f_grad, alpha_num
#pragma unroll
        for (int cl = 0; cl < 4; cl++) {
            int c = ci*16 + cg*4 + cl;
            int gi = ((b*NC + c)*NH + gh)*NW + gw;
            const float4* fp = (const float4*)(fin + gi);
            float4 fa = fp[0], fb4 = fp[1];
            float fg[8];
            fg[0] = fmaf(regw, fa.x, acc[cl][0]);
            fg[1] = fmaf(regw, fa.y, acc[cl][1]);
            fg[2] = fmaf(regw, fa.z, acc[cl][2]);
            fg[3] = fmaf(regw, fa.w, acc[cl][3]);
            fg[4] = fmaf(regw, fb4.x, acc[cl][4]);
            fg[5] = fmaf(regw, fb4.y, acc[cl][5]);
            fg[6] = fmaf(regw, fb4.z, acc[cl][6]);
            fg[7] = fmaf(regw, fb4.w, acc[cl][7]);
            float4* op = (float4*)(g_fgrad + gi);
            op[0] = make_float4(fg[0], fg[1], fg[2], fg[3]);
            op[1] = make_float4(fg[4], fg[5], fg[6], fg[7]);
#pragma unroll
            for (int j = 0; j < 8; j++) anum[j] = fmaf(fg[j], fg[j], anum[j]);
        }
        __syncthreads();
    }
#undef STAGE_CT

    // reduce alpha_num across the 4 warps (channels), write to global
    float* numS = sm;      // reuse mS region (all compute done)
    numS[tid] = 0.f; numS[tid + 128] = 0.f;
    __syncthreads();
#pragma unroll
    for (int j = 0; j < 8; j++)
        atomicAdd(numS + (y*32 + xg*8 + j), anum[j]);
    __syncthreads();
    for (int i = tid; i < 256; i += 128)
        g_anum[b*NHW + (y0 + (i >> 5))*NW + x0 + (i & 31)] = numS[i];
}

// ---------------------------------------------------------------------------
extern "C" void kernel_launch(void* const* d_in, const int* in_sizes, int n_in,
                              void* d_out, int out_size) {
    const float* fmap = (const float*)d_in[0];   // filter_map (b,c,H,W)
    const float* ref  = (const float*)d_in[1];   // reference_feat (b,c,H,W)
    const float* lw   = (const float*)d_in[2];   // label_w (10)
    const float* sw   = (const float*)d_in[3];   // spatial_w (10)
    const float* mw   = (const float*)d_in[4];   // mask_w (10)
    const float* ls   = (const float*)d_in[5];   // log_step_length (1)
    const float* fr   = (const float*)d_in[6];   // filter_reg (1)
    float* out = (float*)d_out;

    cudaFuncSetAttribute(corr_kernel<0>,
                         cudaFuncAttributeMaxDynamicSharedMemorySize, CORR_SMEM);
    cudaFuncSetAttribute(corr_kernel<1>,
                         cudaFuncAttributeMaxDynamicSharedMemorySize, CORR_SMEM);
    cudaFuncSetAttribute(corr_t_kernel,
                         cudaFuncAttributeMaxDynamicSharedMemorySize, CT_SMEM);

    void* p;
    cudaGetSymbolAddress(&p, g_f);     float* gf  = (float*)p;
    cudaGetSymbolAddress(&p, g_fgrad); float* gfg = (float*)p;

    setup_kernel<<<1, 128>>>(lw, sw, mw, ls, fr);

    dim3 grid(NW/TX, NH/TY, NB);   // (4, 16, 4)
    for (int it = 0; it < 3; it++) {
        const float* fin = (it == 0) ? fmap : gf;
        float* fout = (it == 2) ? out : gf;
        corr_kernel<0><<<grid, 320, CORR_SMEM>>>(fin, ref, nullptr, nullptr);  // scores
        corr_t_kernel<<<grid, 128, CT_SMEM>>>(fin, ref);           // f_grad + alpha_num
        corr_kernel<1><<<grid, 320, CORR_SMEM>>>(gfg, ref, fin, fout); // alpha_den + update
    }
}